// round 1
// baseline (speedup 1.0000x reference)
#include <cuda_runtime.h>

// Scratch (allocation-free rule: __device__ globals).
// Max activation size is 8192 x 128 fp32 = 4 MB.
static const int NROWS = 8192;
__device__ __align__(16) float g_Y[NROWS * 128];
__device__ __align__(16) float g_T[NROWS * 128];
__device__ __align__(16) float g_Z[NROWS * 128];

// C = A[M,Kd] * B[Kd,N]
// If EPI: C = (RELU?relu:id)( h0*Ybuf + h1*Tbuf + h2*(A*B) + bias )
template <int BM, int BN, int BK, int TM, int TN, bool EPI, bool RELU>
__global__ void __launch_bounds__((BM / TM) * (BN / TN))
gemm_k(const float* __restrict__ A, const float* __restrict__ B,
       float* __restrict__ C, int M, int Kd, int N,
       const float* __restrict__ Ybuf, const float* __restrict__ Tbuf,
       const float* __restrict__ hv, const float* __restrict__ bias)
{
    constexpr int THREADS = (BM / TM) * (BN / TN);
    constexpr int BMP = BM + 4;  // pad to break bank conflicts on transposed stores
    __shared__ __align__(16) float As[BK][BMP];
    __shared__ __align__(16) float Bs[BK][BN];

    const int tid  = threadIdx.x;
    const int tcol = tid % (BN / TN);
    const int trow = tid / (BN / TN);
    const int by = blockIdx.y * BM;
    const int bx = blockIdx.x * BN;

    float acc[TM][TN];
#pragma unroll
    for (int i = 0; i < TM; i++)
#pragma unroll
        for (int j = 0; j < TN; j++) acc[i][j] = 0.f;

    for (int k0 = 0; k0 < Kd; k0 += BK) {
        // Load A tile (BM x BK), store transposed As[k][m]
#pragma unroll
        for (int i = tid; i < BM * BK / 4; i += THREADS) {
            int r  = i / (BK / 4);
            int c4 = (i % (BK / 4)) * 4;
            float4 v = *(const float4*)(A + (size_t)(by + r) * Kd + k0 + c4);
            As[c4 + 0][r] = v.x;
            As[c4 + 1][r] = v.y;
            As[c4 + 2][r] = v.z;
            As[c4 + 3][r] = v.w;
        }
        // Load B tile (BK x BN) row-major, vectorized
#pragma unroll
        for (int i = tid; i < BK * BN / 4; i += THREADS) {
            int r  = i / (BN / 4);
            int c4 = (i % (BN / 4)) * 4;
            *(float4*)&Bs[r][c4] =
                *(const float4*)(B + (size_t)(k0 + r) * N + bx + c4);
        }
        __syncthreads();

#pragma unroll
        for (int k = 0; k < BK; k++) {
            float ra[TM], rb[TN];
#pragma unroll
            for (int i = 0; i < TM; i += 4) {
                float4 v = *(const float4*)&As[k][trow * TM + i];
                ra[i] = v.x; ra[i + 1] = v.y; ra[i + 2] = v.z; ra[i + 3] = v.w;
            }
#pragma unroll
            for (int j = 0; j < TN; j += 4) {
                float4 v = *(const float4*)&Bs[k][tcol * TN + j];
                rb[j] = v.x; rb[j + 1] = v.y; rb[j + 2] = v.z; rb[j + 3] = v.w;
            }
#pragma unroll
            for (int i = 0; i < TM; i++)
#pragma unroll
                for (int j = 0; j < TN; j++)
                    acc[i][j] = fmaf(ra[i], rb[j], acc[i][j]);
        }
        __syncthreads();
    }

    float c0 = 0.f, c1 = 0.f, c2 = 0.f;
    if (EPI) { c0 = hv[0]; c1 = hv[1]; c2 = hv[2]; }

#pragma unroll
    for (int i = 0; i < TM; i++) {
        const int row = by + trow * TM + i;
#pragma unroll
        for (int j = 0; j < TN; j += 4) {
            const int col = bx + tcol * TN + j;
            float4 v = make_float4(acc[i][j], acc[i][j + 1],
                                   acc[i][j + 2], acc[i][j + 3]);
            if (EPI) {
                const float4 y = *(const float4*)(Ybuf + (size_t)row * N + col);
                const float4 t = *(const float4*)(Tbuf + (size_t)row * N + col);
                const float4 bb = *(const float4*)(bias + col);
                v.x = c0 * y.x + c1 * t.x + c2 * v.x + bb.x;
                v.y = c0 * y.y + c1 * t.y + c2 * v.y + bb.y;
                v.z = c0 * y.z + c1 * t.z + c2 * v.z + bb.z;
                v.w = c0 * y.w + c1 * t.w + c2 * v.w + bb.w;
                if (RELU) {
                    v.x = fmaxf(v.x, 0.f);
                    v.y = fmaxf(v.y, 0.f);
                    v.z = fmaxf(v.z, 0.f);
                    v.w = fmaxf(v.w, 0.f);
                }
            }
            *(float4*)(C + (size_t)row * N + col) = v;
        }
    }
}

extern "C" void kernel_launch(void* const* d_in, const int* in_sizes, int n_in,
                              void* d_out, int out_size)
{
    (void)in_sizes; (void)n_in; (void)out_size;
    const float* S  = (const float*)d_in[0];
    const float* X  = (const float*)d_in[1];
    const float* W1 = (const float*)d_in[2];
    const float* h1 = (const float*)d_in[3];
    const float* b1 = (const float*)d_in[4];
    const float* W2 = (const float*)d_in[5];
    const float* h2 = (const float*)d_in[6];
    const float* b2 = (const float*)d_in[7];
    const float* W3 = (const float*)d_in[8];
    const float* h3 = (const float*)d_in[9];
    const float* b3 = (const float*)d_in[10];
    float* out = (float*)d_out;

    float *Y = nullptr, *T = nullptr, *Z = nullptr;
    cudaGetSymbolAddress((void**)&Y, g_Y);
    cudaGetSymbolAddress((void**)&T, g_T);
    cudaGetSymbolAddress((void**)&Z, g_Z);

    const int M = NROWS;
    dim3 grid(1, M / 64);

    // ---- Layer 1: Y = X@W1; T = S@Y; Z = relu(h0*Y + h1*T + h2*(S@T) + b1)
    gemm_k<64,128,16,8,4,false,false><<<grid, 256>>>(X, W1, Y, M, 512, 128,
                                                     nullptr, nullptr, nullptr, nullptr);
    gemm_k<64,128,16,8,4,false,false><<<grid, 256>>>(S, Y, T, M, M, 128,
                                                     nullptr, nullptr, nullptr, nullptr);
    gemm_k<64,128,16,8,4,true ,true ><<<grid, 256>>>(S, T, Z, M, M, 128,
                                                     Y, T, h1, b1);
    // ---- Layer 2
    gemm_k<64,128,16,8,4,false,false><<<grid, 256>>>(Z, W2, Y, M, 128, 128,
                                                     nullptr, nullptr, nullptr, nullptr);
    gemm_k<64,128,16,8,4,false,false><<<grid, 256>>>(S, Y, T, M, M, 128,
                                                     nullptr, nullptr, nullptr, nullptr);
    gemm_k<64,128,16,8,4,true ,true ><<<grid, 256>>>(S, T, Z, M, M, 128,
                                                     Y, T, h2, b2);
    // ---- Layer 3 (no ReLU), N = 64, writes d_out
    gemm_k<64, 64,16,8,4,false,false><<<grid, 128>>>(Z, W3, Y, M, 128, 64,
                                                     nullptr, nullptr, nullptr, nullptr);
    gemm_k<64, 64,16,8,4,false,false><<<grid, 128>>>(S, Y, T, M, M, 64,
                                                     nullptr, nullptr, nullptr, nullptr);
    gemm_k<64, 64,16,8,4,true ,false><<<grid, 128>>>(S, T, out, M, M, 64,
                                                     Y, T, h3, b3);
}

// round 3
// speedup vs baseline: 2.9525x; 2.9525x over previous
#include <cuda_runtime.h>
#include <cuda_bf16.h>
#include <cstdint>

#define NROWS 8192

// ---------------- scratch (__device__ globals; no allocation allowed) ----------
__device__ __align__(16) float g_Y[NROWS * 128];
__device__ __align__(16) float g_T[NROWS * 128];
__device__ __align__(16) float g_Z[NROWS * 128];
__device__ __align__(16) __nv_bfloat16 g_Bhi[128 * NROWS];   // transposed activations, hi
__device__ __align__(16) __nv_bfloat16 g_Blo[128 * NROWS];   // transposed activations, lo
__device__ __align__(16) __nv_bfloat16 g_Whi[128 * 512];     // transposed weights, hi
__device__ __align__(16) __nv_bfloat16 g_Wlo[128 * 512];     // transposed weights, lo

__device__ __forceinline__ uint32_t smem_u32(const void* p) {
    uint32_t a;
    asm("{ .reg .u64 t; cvta.to.shared.u64 t, %1; cvt.u32.u64 %0, t; }" : "=r"(a) : "l"(p));
    return a;
}

#define LDSM_X4(r, addr)                                                        \
    asm volatile("ldmatrix.sync.aligned.m8n8.x4.shared.b16 {%0,%1,%2,%3}, [%4];"\
                 : "=r"((r)[0]), "=r"((r)[1]), "=r"((r)[2]), "=r"((r)[3])       \
                 : "r"(addr))

#define MMA16816(d, a, b)                                                       \
    asm volatile("mma.sync.aligned.m16n8k16.row.col.f32.bf16.bf16.f32 "         \
                 "{%0,%1,%2,%3}, {%4,%5,%6,%7}, {%8,%9}, {%0,%1,%2,%3};"        \
                 : "+f"((d)[0]), "+f"((d)[1]), "+f"((d)[2]), "+f"((d)[3])       \
                 : "r"((a)[0]), "r"((a)[1]), "r"((a)[2]), "r"((a)[3]),          \
                   "r"((b)[0]), "r"((b)[1]))

// split fp32 pair -> packed bf16 hi pair + lo pair
__device__ __forceinline__ void split2(float a, float b, uint32_t& hi, uint32_t& lo) {
    __nv_bfloat162 H, L;
    H.x = __float2bfloat16(a);
    H.y = __float2bfloat16(b);
    L.x = __float2bfloat16(a - __bfloat162float(H.x));
    L.y = __float2bfloat16(b - __bfloat162float(H.y));
    hi = *reinterpret_cast<uint32_t*>(&H);
    lo = *reinterpret_cast<uint32_t*>(&L);
}

// ---------------- transpose + bf16-split convert: out[c][r] = in[r][c] ---------
__global__ void convt_k(const float* __restrict__ in, __nv_bfloat16* __restrict__ ohi,
                        __nv_bfloat16* __restrict__ olo, int R, int C)
{
    __shared__ float tile[32][33];
    const int bx = blockIdx.x * 32, by = blockIdx.y * 32;
    const int tx = threadIdx.x, ty = threadIdx.y;
#pragma unroll
    for (int i = 0; i < 32; i += 8)
        tile[ty + i][tx] = in[(size_t)(by + ty + i) * C + bx + tx];
    __syncthreads();
#pragma unroll
    for (int i = 0; i < 32; i += 8) {
        float v = tile[tx][ty + i];
        __nv_bfloat16 h = __float2bfloat16(v);
        size_t o = (size_t)(bx + ty + i) * R + by + tx;
        ohi[o] = h;
        olo[o] = __float2bfloat16(v - __bfloat162float(h));
    }
}

// ---------------- HMMA GEMM: C[M,BN] = A[M,K](fp32) * Bt[BN,K](bf16 split) -----
// EPI: C = (RELU?relu:id)(h0*Y + h1*T + h2*acc + bias)
// BM=64, BK=64, 256 threads = 8 warps (2 m x 4 n), warp tile 32 x (BN/4).
template <int BN, bool EPI, bool RELU>
__global__ void __launch_bounds__(256)
tgemm_k(const float* __restrict__ A, int lda,
        const __nv_bfloat16* __restrict__ Bhi, const __nv_bfloat16* __restrict__ Blo,
        int ldb, int Kd, float* __restrict__ C,
        const float* __restrict__ Ybuf, const float* __restrict__ Tbuf,
        const float* __restrict__ hv, const float* __restrict__ bias)
{
    extern __shared__ char sm[];
    constexpr int LDE = 72;                 // smem row stride, elems (144 B)
    constexpr int LDBY = LDE * 2;           // 144 bytes
    constexpr int ASZ = 64 * LDBY;          // 9216 B (one of Ahi/Alo)
    constexpr int BSZ = BN * LDBY;          // Bhi/Blo each
    constexpr int STAGE = 2 * ASZ + 2 * BSZ;
    constexpr int WN = BN / 4;              // warp n extent (32 or 16)
    constexpr int NT = WN / 8;              // n8 tiles per warp (4 or 2)
    constexpr int BIT = BN / 32;            // B global-load iters per split

    const int tid = threadIdx.x;
    const int wid = tid >> 5, lid = tid & 31;
    const int wm = wid & 1, wn = wid >> 1;
    const int m0 = blockIdx.x * 64;
    const uint32_t smb = smem_u32(sm);

    // A global mapping: 4 threads/row, 16 elems each (4 float4)
    const int arow = tid >> 2, aq = tid & 3;
    const float* aptr = A + (size_t)(m0 + arow) * lda + aq * 16;
    const uint32_t a_st = arow * LDBY + aq * 32;     // byte offset of first elem

    // ldmatrix lane offsets (bytes)
    const uint32_t a_ln = (lid & 15) * LDBY + (lid >> 4) * 16;
    const uint32_t b_ln = ((lid & 7) + ((lid >> 4) << 3)) * LDBY + ((lid >> 3) & 1) * 16;

    float acc[2][NT][4];
#pragma unroll
    for (int mt = 0; mt < 2; mt++)
#pragma unroll
        for (int nt = 0; nt < NT; nt++)
#pragma unroll
            for (int j = 0; j < 4; j++) acc[mt][nt][j] = 0.f;

    const int nk = Kd / 64;
    float4 av[4];
    uint4 bhv[BIT], blv[BIT];

    // ---- prologue: load chunk 0, store to stage 0 ----
    {
        const float4* ap = (const float4*)(aptr);
#pragma unroll
        for (int j = 0; j < 4; j++) av[j] = ap[j];
#pragma unroll
        for (int it = 0; it < BIT; it++) {
            int idx = tid + it * 256;
            int br = idx >> 3, seg = idx & 7;
            size_t go = (size_t)br * ldb + seg * 8;
            bhv[it] = *(const uint4*)(Bhi + go);
            blv[it] = *(const uint4*)(Blo + go);
        }
        char* ah = sm;
        char* al = sm + ASZ;
        char* bh = sm + 2 * ASZ;
        char* bl = bh + BSZ;
#pragma unroll
        for (int j = 0; j < 4; j++) {
            uint2 H, L;
            split2(av[j].x, av[j].y, H.x, L.x);
            split2(av[j].z, av[j].w, H.y, L.y);
            *(uint2*)(ah + a_st + j * 8) = H;
            *(uint2*)(al + a_st + j * 8) = L;
        }
#pragma unroll
        for (int it = 0; it < BIT; it++) {
            int idx = tid + it * 256;
            int br = idx >> 3, seg = idx & 7;
            uint32_t s = br * LDBY + seg * 16;
            *(uint4*)(bh + s) = bhv[it];
            *(uint4*)(bl + s) = blv[it];
        }
    }
    __syncthreads();

    for (int ch = 0; ch < nk; ch++) {
        const int b = ch & 1;
        // ---- prefetch next chunk into registers (hides gmem latency under MMA)
        if (ch + 1 < nk) {
            const float4* ap = (const float4*)(aptr + (ch + 1) * 64);
#pragma unroll
            for (int j = 0; j < 4; j++) av[j] = ap[j];
#pragma unroll
            for (int it = 0; it < BIT; it++) {
                int idx = tid + it * 256;
                int br = idx >> 3, seg = idx & 7;
                size_t go = (size_t)br * ldb + (ch + 1) * 64 + seg * 8;
                bhv[it] = *(const uint4*)(Bhi + go);
                blv[it] = *(const uint4*)(Blo + go);
            }
        }
        // ---- compute from stage b ----
        const uint32_t ahb = smb + b * STAGE;
        const uint32_t alb = ahb + ASZ;
        const uint32_t bhb = ahb + 2 * ASZ;
        const uint32_t blb = bhb + BSZ;
#pragma unroll
        for (int ks = 0; ks < 4; ks++) {
            uint32_t ah[2][4], al2[2][4];
#pragma unroll
            for (int mt = 0; mt < 2; mt++) {
                uint32_t ro = (wm * 32 + mt * 16) * LDBY + ks * 32;
                LDSM_X4(ah[mt], ahb + ro + a_ln);
                LDSM_X4(al2[mt], alb + ro + a_ln);
            }
            uint32_t bh[NT][2], bl[NT][2];
#pragma unroll
            for (int p = 0; p < NT / 2; p++) {
                uint32_t ro = (wn * WN + p * 16) * LDBY + ks * 32;
                uint32_t t[4];
                LDSM_X4(t, bhb + ro + b_ln);
                bh[2 * p][0] = t[0]; bh[2 * p][1] = t[1];
                bh[2 * p + 1][0] = t[2]; bh[2 * p + 1][1] = t[3];
                LDSM_X4(t, blb + ro + b_ln);
                bl[2 * p][0] = t[0]; bl[2 * p][1] = t[1];
                bl[2 * p + 1][0] = t[2]; bl[2 * p + 1][1] = t[3];
            }
#pragma unroll
            for (int mt = 0; mt < 2; mt++)
#pragma unroll
                for (int nt = 0; nt < NT; nt++) {
                    MMA16816(acc[mt][nt], ah[mt], bh[nt]);
                    MMA16816(acc[mt][nt], ah[mt], bl[nt]);
                    MMA16816(acc[mt][nt], al2[mt], bh[nt]);
                }
        }
        __syncthreads();   // all warps done reading stage b
        // ---- store prefetched chunk to the other stage ----
        if (ch + 1 < nk) {
            char* ah = sm + (b ^ 1) * STAGE;
            char* al = ah + ASZ;
            char* bh = ah + 2 * ASZ;
            char* bl = bh + BSZ;
#pragma unroll
            for (int j = 0; j < 4; j++) {
                uint2 H, L;
                split2(av[j].x, av[j].y, H.x, L.x);
                split2(av[j].z, av[j].w, H.y, L.y);
                *(uint2*)(ah + a_st + j * 8) = H;
                *(uint2*)(al + a_st + j * 8) = L;
            }
#pragma unroll
            for (int it = 0; it < BIT; it++) {
                int idx = tid + it * 256;
                int br = idx >> 3, seg = idx & 7;
                uint32_t s = br * LDBY + seg * 16;
                *(uint4*)(bh + s) = bhv[it];
                *(uint4*)(bl + s) = blv[it];
            }
            __syncthreads();
        }
    }

    // ---- epilogue ----
    float c0 = 0.f, c1 = 0.f, c2 = 0.f;
    if (EPI) { c0 = hv[0]; c1 = hv[1]; c2 = hv[2]; }
#pragma unroll
    for (int mt = 0; mt < 2; mt++) {
#pragma unroll
        for (int half = 0; half < 2; half++) {
            const int row = m0 + wm * 32 + mt * 16 + (lid >> 2) + half * 8;
#pragma unroll
            for (int nt = 0; nt < NT; nt++) {
                const int col = wn * WN + nt * 8 + (lid & 3) * 2;
                float2 v = make_float2(acc[mt][nt][half * 2 + 0],
                                       acc[mt][nt][half * 2 + 1]);
                if (EPI) {
                    const float2 y = *(const float2*)(Ybuf + (size_t)row * BN + col);
                    const float2 t = *(const float2*)(Tbuf + (size_t)row * BN + col);
                    const float2 bb = *(const float2*)(bias + col);
                    v.x = c0 * y.x + c1 * t.x + c2 * v.x + bb.x;
                    v.y = c0 * y.y + c1 * t.y + c2 * v.y + bb.y;
                    if (RELU) { v.x = fmaxf(v.x, 0.f); v.y = fmaxf(v.y, 0.f); }
                }
                *(float2*)(C + (size_t)row * BN + col) = v;
            }
        }
    }
}

// -------------------------------------------------------------------------------
extern "C" void kernel_launch(void* const* d_in, const int* in_sizes, int n_in,
                              void* d_out, int out_size)
{
    (void)in_sizes; (void)n_in; (void)out_size;
    const float* S  = (const float*)d_in[0];
    const float* X  = (const float*)d_in[1];
    const float* W1 = (const float*)d_in[2];
    const float* h1 = (const float*)d_in[3];
    const float* b1 = (const float*)d_in[4];
    const float* W2 = (const float*)d_in[5];
    const float* h2 = (const float*)d_in[6];
    const float* b2 = (const float*)d_in[7];
    const float* W3 = (const float*)d_in[8];
    const float* h3 = (const float*)d_in[9];
    const float* b3 = (const float*)d_in[10];
    float* out = (float*)d_out;

    float *Y, *T, *Z;
    __nv_bfloat16 *Bhi, *Blo, *Whi, *Wlo;
    cudaGetSymbolAddress((void**)&Y, g_Y);
    cudaGetSymbolAddress((void**)&T, g_T);
    cudaGetSymbolAddress((void**)&Z, g_Z);
    cudaGetSymbolAddress((void**)&Bhi, g_Bhi);
    cudaGetSymbolAddress((void**)&Blo, g_Blo);
    cudaGetSymbolAddress((void**)&Whi, g_Whi);
    cudaGetSymbolAddress((void**)&Wlo, g_Wlo);

    // dynamic smem: STAGE = 2*9216 + 2*BN*144, double-buffered
    const int SM128 = 2 * (2 * 9216 + 2 * 128 * 144);  // 110592
    const int SM64  = 2 * (2 * 9216 + 2 * 64 * 144);   //  73728
    cudaFuncSetAttribute(tgemm_k<128, false, false>, cudaFuncAttributeMaxDynamicSharedMemorySize, SM128);
    cudaFuncSetAttribute(tgemm_k<128, true,  true >, cudaFuncAttributeMaxDynamicSharedMemorySize, SM128);
    cudaFuncSetAttribute(tgemm_k<64,  false, false>, cudaFuncAttributeMaxDynamicSharedMemorySize, SM64);
    cudaFuncSetAttribute(tgemm_k<64,  true,  false>, cudaFuncAttributeMaxDynamicSharedMemorySize, SM64);

    const dim3 g(NROWS / 64);
    const dim3 blk(256);
    const dim3 tb(32, 8);

    // ================= Layer 1 (in=512, out=128) =================
    convt_k<<<dim3(128 / 32, 512 / 32), tb>>>(W1, Whi, Wlo, 512, 128);
    tgemm_k<128, false, false><<<g, blk, SM128>>>(X, 512, Whi, Wlo, 512, 512, Y,
                                                  nullptr, nullptr, nullptr, nullptr);
    convt_k<<<dim3(128 / 32, NROWS / 32), tb>>>(Y, Bhi, Blo, NROWS, 128);
    tgemm_k<128, false, false><<<g, blk, SM128>>>(S, NROWS, Bhi, Blo, NROWS, NROWS, T,
                                                  nullptr, nullptr, nullptr, nullptr);
    convt_k<<<dim3(128 / 32, NROWS / 32), tb>>>(T, Bhi, Blo, NROWS, 128);
    tgemm_k<128, true, true><<<g, blk, SM128>>>(S, NROWS, Bhi, Blo, NROWS, NROWS, Z,
                                                Y, T, h1, b1);
    // ================= Layer 2 (128 -> 128) =================
    convt_k<<<dim3(128 / 32, 128 / 32), tb>>>(W2, Whi, Wlo, 128, 128);
    tgemm_k<128, false, false><<<g, blk, SM128>>>(Z, 128, Whi, Wlo, 128, 128, Y,
                                                  nullptr, nullptr, nullptr, nullptr);
    convt_k<<<dim3(128 / 32, NROWS / 32), tb>>>(Y, Bhi, Blo, NROWS, 128);
    tgemm_k<128, false, false><<<g, blk, SM128>>>(S, NROWS, Bhi, Blo, NROWS, NROWS, T,
                                                  nullptr, nullptr, nullptr, nullptr);
    convt_k<<<dim3(128 / 32, NROWS / 32), tb>>>(T, Bhi, Blo, NROWS, 128);
    tgemm_k<128, true, true><<<g, blk, SM128>>>(S, NROWS, Bhi, Blo, NROWS, NROWS, Z,
                                                Y, T, h2, b2);
    // ================= Layer 3 (128 -> 64, no ReLU) =================
    convt_k<<<dim3(64 / 32, 128 / 32), tb>>>(W3, Whi, Wlo, 128, 64);
    tgemm_k<64, false, false><<<g, blk, SM64>>>(Z, 128, Whi, Wlo, 128, 128, Y,
                                                nullptr, nullptr, nullptr, nullptr);
    convt_k<<<dim3(64 / 32, NROWS / 32), tb>>>(Y, Bhi, Blo, NROWS, 64);
    tgemm_k<64, false, false><<<g, blk, SM64>>>(S, NROWS, Bhi, Blo, NROWS, NROWS, T,
                                                nullptr, nullptr, nullptr, nullptr);
    convt_k<<<dim3(64 / 32, NROWS / 32), tb>>>(T, Bhi, Blo, NROWS, 64);
    tgemm_k<64, true, false><<<g, blk, SM64>>>(S, NROWS, Bhi, Blo, NROWS, NROWS, out,
                                               Y, T, h3, b3);
}

// round 4
// speedup vs baseline: 4.8394x; 1.6391x over previous
#include <cuda_runtime.h>
#include <cuda_bf16.h>
#include <cstdint>

#define NROWS 8192

// ---------------- scratch (__device__ globals; no allocation allowed) ----------
__device__ __align__(16) float g_Y[NROWS * 128];
__device__ __align__(16) float g_T[NROWS * 128];
__device__ __align__(16) float g_Z[NROWS * 128];
__device__ __align__(16) __nv_bfloat16 g_Shi[(size_t)NROWS * NROWS];  // 128 MB
__device__ __align__(16) __nv_bfloat16 g_Slo[(size_t)NROWS * NROWS];  // 128 MB
__device__ __align__(16) __nv_bfloat16 g_Ahi[NROWS * 512];
__device__ __align__(16) __nv_bfloat16 g_Alo[NROWS * 512];
__device__ __align__(16) __nv_bfloat16 g_Bhi[128 * NROWS];
__device__ __align__(16) __nv_bfloat16 g_Blo[128 * NROWS];
__device__ __align__(16) __nv_bfloat16 g_Whi[128 * 512];
__device__ __align__(16) __nv_bfloat16 g_Wlo[128 * 512];

__device__ __forceinline__ uint32_t smem_u32(const void* p) {
    uint32_t a;
    asm("{ .reg .u64 t; cvta.to.shared.u64 t, %1; cvt.u32.u64 %0, t; }" : "=r"(a) : "l"(p));
    return a;
}

#define LDSM_X4(r, addr)                                                        \
    asm volatile("ldmatrix.sync.aligned.m8n8.x4.shared.b16 {%0,%1,%2,%3}, [%4];"\
                 : "=r"((r)[0]), "=r"((r)[1]), "=r"((r)[2]), "=r"((r)[3])       \
                 : "r"(addr))

#define MMA16816(d, a, b)                                                       \
    asm volatile("mma.sync.aligned.m16n8k16.row.col.f32.bf16.bf16.f32 "         \
                 "{%0,%1,%2,%3}, {%4,%5,%6,%7}, {%8,%9}, {%0,%1,%2,%3};"        \
                 : "+f"((d)[0]), "+f"((d)[1]), "+f"((d)[2]), "+f"((d)[3])       \
                 : "r"((a)[0]), "r"((a)[1]), "r"((a)[2]), "r"((a)[3]),          \
                   "r"((b)[0]), "r"((b)[1]))

#define CP16(s, g)                                                              \
    asm volatile("cp.async.cg.shared.global [%0], [%1], 16;"                    \
                 :: "r"(s), "l"(g) : "memory")
#define CP_COMMIT() asm volatile("cp.async.commit_group;" ::: "memory")
#define CP_WAIT(n)  asm volatile("cp.async.wait_group %0;" :: "n"(n) : "memory")

// split fp32 pair -> packed bf16 hi pair + lo pair
__device__ __forceinline__ void split2(float a, float b, uint32_t& hi, uint32_t& lo) {
    __nv_bfloat162 H, L;
    H.x = __float2bfloat16(a);
    H.y = __float2bfloat16(b);
    L.x = __float2bfloat16(a - __bfloat162float(H.x));
    L.y = __float2bfloat16(b - __bfloat162float(H.y));
    hi = *reinterpret_cast<uint32_t*>(&H);
    lo = *reinterpret_cast<uint32_t*>(&L);
}

// ---------------- row-major bf16 split: ohi/olo[i] = split(in[i]) --------------
__global__ void split_k(const float* __restrict__ in, __nv_bfloat16* __restrict__ ohi,
                        __nv_bfloat16* __restrict__ olo)
{
    size_t i = ((size_t)blockIdx.x * 256 + threadIdx.x) * 8;
    float4 v0 = *(const float4*)(in + i);
    float4 v1 = *(const float4*)(in + i + 4);
    uint4 H, L;
    split2(v0.x, v0.y, H.x, L.x);
    split2(v0.z, v0.w, H.y, L.y);
    split2(v1.x, v1.y, H.z, L.z);
    split2(v1.z, v1.w, H.w, L.w);
    *(uint4*)(ohi + i) = H;
    *(uint4*)(olo + i) = L;
}

// ---------------- transpose + bf16-split convert: out[c][r] = in[r][c] ---------
__global__ void convt_k(const float* __restrict__ in, __nv_bfloat16* __restrict__ ohi,
                        __nv_bfloat16* __restrict__ olo, int R, int C)
{
    __shared__ float tile[32][33];
    const int bx = blockIdx.x * 32, by = blockIdx.y * 32;
    const int tx = threadIdx.x, ty = threadIdx.y;
#pragma unroll
    for (int i = 0; i < 32; i += 8)
        tile[ty + i][tx] = in[(size_t)(by + ty + i) * C + bx + tx];
    __syncthreads();
#pragma unroll
    for (int i = 0; i < 32; i += 8) {
        float v = tile[tx][ty + i];
        __nv_bfloat16 h = __float2bfloat16(v);
        size_t o = (size_t)(bx + ty + i) * R + by + tx;
        ohi[o] = h;
        olo[o] = __float2bfloat16(v - __bfloat162float(h));
    }
}

// ---------------- HMMA GEMM: C[M,BN] = A[M,K] x Bt[BN,K], both bf16 hi/lo ------
// BM=64, BK=64, 256 thr = 8 warps (2m x 4n). cp.async D-stage pipeline,
// XOR-swizzled smem, register double-buffered fragments.
// EPI: C = (RELU?relu:id)(h0*Y + h1*T + h2*acc + bias)
template <int BN, int D, bool EPI, bool RELU>
__global__ void __launch_bounds__(256)
tgemm_k(const __nv_bfloat16* __restrict__ Ahi, const __nv_bfloat16* __restrict__ Alo,
        int lda,
        const __nv_bfloat16* __restrict__ Bhi, const __nv_bfloat16* __restrict__ Blo,
        int ldb, int Kd, float* __restrict__ C,
        const float* __restrict__ Ybuf, const float* __restrict__ Tbuf,
        const float* __restrict__ hv, const float* __restrict__ bias)
{
    extern __shared__ char sm[];
    constexpr int WN = BN / 4;          // warp n extent
    constexpr int NT = WN / 8;          // n8 tiles per warp
    constexpr int ASPL = 64 * 128;      // bytes per A split tile
    constexpr int BSPL = BN * 128;      // bytes per B split tile
    constexpr int STAGE = 2 * ASPL + 2 * BSPL;

    const int tid = threadIdx.x, wid = tid >> 5, lid = tid & 31;
    const int wm = wid & 1, wn = wid >> 1;
    const int m0 = blockIdx.x * 64;
    const uint32_t smb = smem_u32(sm);

    // cp.async per-thread mapping: 16B chunk id = tid + 256*it -> row=id>>3, c=id&7
    const int ldrow = tid >> 3, ldc = tid & 7;

    // LDSM lane decomposition (same fragment mapping as validated R3 kernel)
    const int arl = lid & 15, ahf = lid >> 4;               // A: row lane, 16B half
    const int brl = (lid & 7) + ((lid >> 4) << 3);          // B: row lane
    const int bhf = (lid >> 3) & 1;                         // B: 16B half
    const int asw = arl & 7, bsw = lid & 7;                 // swizzle keys

    float acc[2][NT][4];
#pragma unroll
    for (int mt = 0; mt < 2; mt++)
#pragma unroll
        for (int nt = 0; nt < NT; nt++)
#pragma unroll
            for (int j = 0; j < 4; j++) acc[mt][nt][j] = 0.f;

    const int nk = Kd / 64;

    auto issue = [&](int ch, int buf) {
        const uint32_t sb = smb + buf * STAGE;
#pragma unroll
        for (int it = 0; it < 2; it++) {
            const int row = ldrow + 32 * it;
            const size_t go = (size_t)(m0 + row) * lda + ch * 64 + ldc * 8;
            const uint32_t so = sb + row * 128 + ((ldc ^ (row & 7)) << 4);
            CP16(so, (const void*)(Ahi + go));
            CP16(so + ASPL, (const void*)(Alo + go));
        }
#pragma unroll
        for (int it = 0; it < BN / 32; it++) {
            const int row = ldrow + 32 * it;
            const size_t go = (size_t)row * ldb + ch * 64 + ldc * 8;
            const uint32_t so = sb + 2 * ASPL + row * 128 + ((ldc ^ (row & 7)) << 4);
            CP16(so, (const void*)(Bhi + go));
            CP16(so + BSPL, (const void*)(Blo + go));
        }
    };

    // prologue: commit exactly D-1 groups (empty if past K)
#pragma unroll
    for (int s = 0; s < D - 1; s++) {
        if (s < nk) issue(s, s);
        CP_COMMIT();
    }

    uint32_t aH[2][2][4], aL[2][2][4], bH[2][NT][2], bL[2][NT][2];

#define FETCH(ks, pb, cab, cbb) do {                                            \
    _Pragma("unroll")                                                           \
    for (int mt = 0; mt < 2; mt++) {                                            \
        const uint32_t ao = (uint32_t)((wm * 32 + mt * 16 + arl) * 128)         \
                          + (uint32_t)((((ks) * 2 + ahf) ^ asw) << 4);          \
        LDSM_X4(aH[pb][mt], (cab) + ao);                                        \
        LDSM_X4(aL[pb][mt], (cab) + ASPL + ao);                                 \
    }                                                                           \
    _Pragma("unroll")                                                           \
    for (int p = 0; p < NT / 2; p++) {                                          \
        const uint32_t bo = (uint32_t)((wn * WN + p * 16 + brl) * 128)          \
                          + (uint32_t)((((ks) * 2 + bhf) ^ bsw) << 4);          \
        LDSM_X4(&bH[pb][2 * p][0], (cbb) + bo);                                 \
        LDSM_X4(&bL[pb][2 * p][0], (cbb) + BSPL + bo);                          \
    }                                                                           \
} while (0)

    for (int i = 0; i < nk; i++) {
        CP_WAIT(D - 2);          // chunk i resident
        __syncthreads();         // all warps past chunk i-1's compute
        if (i + D - 1 < nk) issue(i + D - 1, (i + D - 1) % D);  // into buf (i-1)%D
        CP_COMMIT();

        const uint32_t cab = smb + (i % D) * STAGE;
        const uint32_t cbb = cab + 2 * ASPL;

        FETCH(0, 0, cab, cbb);
#pragma unroll
        for (int ks = 0; ks < 4; ks++) {
            if (ks < 3) FETCH(ks + 1, (ks + 1) & 1, cab, cbb);
            const int pb = ks & 1;
#pragma unroll
            for (int mt = 0; mt < 2; mt++)
#pragma unroll
                for (int nt = 0; nt < NT; nt++) {
                    MMA16816(acc[mt][nt], aH[pb][mt], bH[pb][nt]);
                    MMA16816(acc[mt][nt], aH[pb][mt], bL[pb][nt]);
                    MMA16816(acc[mt][nt], aL[pb][mt], bH[pb][nt]);
                }
        }
    }
#undef FETCH

    // ---- epilogue ----
    float c0 = 0.f, c1 = 0.f, c2 = 0.f;
    if (EPI) { c0 = hv[0]; c1 = hv[1]; c2 = hv[2]; }
#pragma unroll
    for (int mt = 0; mt < 2; mt++) {
#pragma unroll
        for (int half = 0; half < 2; half++) {
            const int row = m0 + wm * 32 + mt * 16 + (lid >> 2) + half * 8;
#pragma unroll
            for (int nt = 0; nt < NT; nt++) {
                const int col = wn * WN + nt * 8 + (lid & 3) * 2;
                float2 v = make_float2(acc[mt][nt][half * 2 + 0],
                                       acc[mt][nt][half * 2 + 1]);
                if (EPI) {
                    const float2 y = *(const float2*)(Ybuf + (size_t)row * BN + col);
                    const float2 t = *(const float2*)(Tbuf + (size_t)row * BN + col);
                    const float2 bb = *(const float2*)(bias + col);
                    v.x = c0 * y.x + c1 * t.x + c2 * v.x + bb.x;
                    v.y = c0 * y.y + c1 * t.y + c2 * v.y + bb.y;
                    if (RELU) { v.x = fmaxf(v.x, 0.f); v.y = fmaxf(v.y, 0.f); }
                }
                *(float2*)(C + (size_t)row * BN + col) = v;
            }
        }
    }
}

// -------------------------------------------------------------------------------
extern "C" void kernel_launch(void* const* d_in, const int* in_sizes, int n_in,
                              void* d_out, int out_size)
{
    (void)in_sizes; (void)n_in; (void)out_size;
    const float* S  = (const float*)d_in[0];
    const float* X  = (const float*)d_in[1];
    const float* W1 = (const float*)d_in[2];
    const float* h1 = (const float*)d_in[3];
    const float* b1 = (const float*)d_in[4];
    const float* W2 = (const float*)d_in[5];
    const float* h2 = (const float*)d_in[6];
    const float* b2 = (const float*)d_in[7];
    const float* W3 = (const float*)d_in[8];
    const float* h3 = (const float*)d_in[9];
    const float* b3 = (const float*)d_in[10];
    float* out = (float*)d_out;

    float *Y, *T, *Z;
    __nv_bfloat16 *Shi, *Slo, *Ahi, *Alo, *Bhi, *Blo, *Whi, *Wlo;
    cudaGetSymbolAddress((void**)&Y, g_Y);
    cudaGetSymbolAddress((void**)&T, g_T);
    cudaGetSymbolAddress((void**)&Z, g_Z);
    cudaGetSymbolAddress((void**)&Shi, g_Shi);
    cudaGetSymbolAddress((void**)&Slo, g_Slo);
    cudaGetSymbolAddress((void**)&Ahi, g_Ahi);
    cudaGetSymbolAddress((void**)&Alo, g_Alo);
    cudaGetSymbolAddress((void**)&Bhi, g_Bhi);
    cudaGetSymbolAddress((void**)&Blo, g_Blo);
    cudaGetSymbolAddress((void**)&Whi, g_Whi);
    cudaGetSymbolAddress((void**)&Wlo, g_Wlo);

    const int SMW = 3 * (2 * 64 * 128 + 2 * 128 * 128);  // 147456 (BN=128, D=3)
    const int SMN = 4 * (2 * 64 * 128 + 2 * 64 * 128);   // 131072 (BN=64,  D=4)
    cudaFuncSetAttribute(tgemm_k<128, 3, false, false>, cudaFuncAttributeMaxDynamicSharedMemorySize, SMW);
    cudaFuncSetAttribute(tgemm_k<128, 3, true,  true >, cudaFuncAttributeMaxDynamicSharedMemorySize, SMW);
    cudaFuncSetAttribute(tgemm_k<64,  4, false, false>, cudaFuncAttributeMaxDynamicSharedMemorySize, SMN);
    cudaFuncSetAttribute(tgemm_k<64,  4, true,  false>, cudaFuncAttributeMaxDynamicSharedMemorySize, SMN);

    const dim3 g(NROWS / 64);
    const dim3 blk(256);
    const dim3 tb(32, 8);

    // one-time splits of the fp32 A-side operands
    split_k<<<(size_t)NROWS * NROWS / 2048, 256>>>(S, Shi, Slo);
    split_k<<<NROWS * 512 / 2048, 256>>>(X, Ahi, Alo);

    // ================= Layer 1 (in=512, out=128) =================
    convt_k<<<dim3(4, 16), tb>>>(W1, Whi, Wlo, 512, 128);
    tgemm_k<128, 3, false, false><<<g, blk, SMW>>>(Ahi, Alo, 512, Whi, Wlo, 512, 512, Y,
                                                   nullptr, nullptr, nullptr, nullptr);
    convt_k<<<dim3(4, 256), tb>>>(Y, Bhi, Blo, NROWS, 128);
    tgemm_k<128, 3, false, false><<<g, blk, SMW>>>(Shi, Slo, NROWS, Bhi, Blo, NROWS, NROWS, T,
                                                   nullptr, nullptr, nullptr, nullptr);
    convt_k<<<dim3(4, 256), tb>>>(T, Bhi, Blo, NROWS, 128);
    tgemm_k<128, 3, true, true><<<g, blk, SMW>>>(Shi, Slo, NROWS, Bhi, Blo, NROWS, NROWS, Z,
                                                 Y, T, h1, b1);
    // ================= Layer 2 (128 -> 128) =================
    split_k<<<NROWS * 128 / 2048, 256>>>(Z, Ahi, Alo);
    convt_k<<<dim3(4, 4), tb>>>(W2, Whi, Wlo, 128, 128);
    tgemm_k<128, 3, false, false><<<g, blk, SMW>>>(Ahi, Alo, 128, Whi, Wlo, 128, 128, Y,
                                                   nullptr, nullptr, nullptr, nullptr);
    convt_k<<<dim3(4, 256), tb>>>(Y, Bhi, Blo, NROWS, 128);
    tgemm_k<128, 3, false, false><<<g, blk, SMW>>>(Shi, Slo, NROWS, Bhi, Blo, NROWS, NROWS, T,
                                                   nullptr, nullptr, nullptr, nullptr);
    convt_k<<<dim3(4, 256), tb>>>(T, Bhi, Blo, NROWS, 128);
    tgemm_k<128, 3, true, true><<<g, blk, SMW>>>(Shi, Slo, NROWS, Bhi, Blo, NROWS, NROWS, Z,
                                                 Y, T, h2, b2);
    // ================= Layer 3 (128 -> 64, no ReLU) =================
    split_k<<<NROWS * 128 / 2048, 256>>>(Z, Ahi, Alo);
    convt_k<<<dim3(2, 4), tb>>>(W3, Whi, Wlo, 128, 64);
    tgemm_k<64, 4, false, false><<<g, blk, SMN>>>(Ahi, Alo, 128, Whi, Wlo, 128, 128, Y,
                                                  nullptr, nullptr, nullptr, nullptr);
    convt_k<<<dim3(2, 256), tb>>>(Y, Bhi, Blo, NROWS, 64);
    tgemm_k<64, 4, false, false><<<g, blk, SMN>>>(Shi, Slo, NROWS, Bhi, Blo, NROWS, NROWS, T,
                                                  nullptr, nullptr, nullptr, nullptr);
    convt_k<<<dim3(2, 256), tb>>>(T, Bhi, Blo, NROWS, 64);
    tgemm_k<64, 4, true, false><<<g, blk, SMN>>>(Shi, Slo, NROWS, Bhi, Blo, NROWS, NROWS, out,
                                                 Y, T, h3, b3);
}

// round 6
// speedup vs baseline: 5.1660x; 1.0675x over previous
#include <cuda_runtime.h>
#include <cuda_bf16.h>
#include <cstdint>

#define NROWS 8192

// ---------------- scratch (__device__ globals; no allocation allowed) ----------
__device__ __align__(16) float g_Y[NROWS * 128];
__device__ __align__(16) float g_T[NROWS * 128];
__device__ __align__(16) float g_Z[NROWS * 128];
__device__ __align__(16) float g_P[2 * NROWS * 128];                  // split-K partials
__device__ __align__(16) __nv_bfloat16 g_Shi[(size_t)NROWS * NROWS];  // 128 MB
__device__ __align__(16) __nv_bfloat16 g_Slo[(size_t)NROWS * NROWS];  // 128 MB
__device__ __align__(16) __nv_bfloat16 g_Ahi[NROWS * 512];
__device__ __align__(16) __nv_bfloat16 g_Alo[NROWS * 512];
__device__ __align__(16) __nv_bfloat16 g_Bhi[128 * NROWS];
__device__ __align__(16) __nv_bfloat16 g_Blo[128 * NROWS];
__device__ __align__(16) __nv_bfloat16 g_Whi[128 * 512];
__device__ __align__(16) __nv_bfloat16 g_Wlo[128 * 512];

__device__ __forceinline__ uint32_t smem_u32(const void* p) {
    uint32_t a;
    asm("{ .reg .u64 t; cvta.to.shared.u64 t, %1; cvt.u32.u64 %0, t; }" : "=r"(a) : "l"(p));
    return a;
}

#define LDSM_X4(r, addr)                                                        \
    asm volatile("ldmatrix.sync.aligned.m8n8.x4.shared.b16 {%0,%1,%2,%3}, [%4];"\
                 : "=r"((r)[0]), "=r"((r)[1]), "=r"((r)[2]), "=r"((r)[3])       \
                 : "r"(addr))

#define MMA16816(d, a, b)                                                       \
    asm volatile("mma.sync.aligned.m16n8k16.row.col.f32.bf16.bf16.f32 "         \
                 "{%0,%1,%2,%3}, {%4,%5,%6,%7}, {%8,%9}, {%0,%1,%2,%3};"        \
                 : "+f"((d)[0]), "+f"((d)[1]), "+f"((d)[2]), "+f"((d)[3])       \
                 : "r"((a)[0]), "r"((a)[1]), "r"((a)[2]), "r"((a)[3]),          \
                   "r"((b)[0]), "r"((b)[1]))

#define CP16(s, g)                                                              \
    asm volatile("cp.async.cg.shared.global [%0], [%1], 16;"                    \
                 :: "r"(s), "l"(g) : "memory")
#define CP_COMMIT() asm volatile("cp.async.commit_group;" ::: "memory")
#define CP_WAIT(n)  asm volatile("cp.async.wait_group %0;" :: "n"(n) : "memory")

__device__ __forceinline__ void split2(float a, float b, uint32_t& hi, uint32_t& lo) {
    __nv_bfloat162 H, L;
    H.x = __float2bfloat16(a);
    H.y = __float2bfloat16(b);
    L.x = __float2bfloat16(a - __bfloat162float(H.x));
    L.y = __float2bfloat16(b - __bfloat162float(H.y));
    hi = *reinterpret_cast<uint32_t*>(&H);
    lo = *reinterpret_cast<uint32_t*>(&L);
}

// ---------------- row-major bf16 split ----------------------------------------
__global__ void split_k(const float* __restrict__ in, __nv_bfloat16* __restrict__ ohi,
                        __nv_bfloat16* __restrict__ olo)
{
    size_t i = ((size_t)blockIdx.x * 256 + threadIdx.x) * 8;
    float4 v0 = *(const float4*)(in + i);
    float4 v1 = *(const float4*)(in + i + 4);
    uint4 H, L;
    split2(v0.x, v0.y, H.x, L.x);
    split2(v0.z, v0.w, H.y, L.y);
    split2(v1.x, v1.y, H.z, L.z);
    split2(v1.z, v1.w, H.w, L.w);
    *(uint4*)(ohi + i) = H;
    *(uint4*)(olo + i) = L;
}

// ---------------- transpose + split: out[c][r] = in[r][c] ----------------------
__global__ void convt_k(const float* __restrict__ in, __nv_bfloat16* __restrict__ ohi,
                        __nv_bfloat16* __restrict__ olo, int R, int C)
{
    __shared__ float tile[32][33];
    const int bx = blockIdx.x * 32, by = blockIdx.y * 32;
    const int tx = threadIdx.x, ty = threadIdx.y;
#pragma unroll
    for (int i = 0; i < 32; i += 8)
        tile[ty + i][tx] = in[(size_t)(by + ty + i) * C + bx + tx];
    __syncthreads();
#pragma unroll
    for (int i = 0; i < 32; i += 8) {
        float v = tile[tx][ty + i];
        __nv_bfloat16 h = __float2bfloat16(v);
        size_t o = (size_t)(bx + ty + i) * R + by + tx;
        ohi[o] = h;
        olo[o] = __float2bfloat16(v - __bfloat162float(h));
    }
}

// ---------------- combine split-K partials + transpose-split -------------------
// T = P0 + P1 (row-major), Bt hi/lo = transposed split of T.
__global__ void combine_t_k(const float* __restrict__ P0, const float* __restrict__ P1,
                            float* __restrict__ T,
                            __nv_bfloat16* __restrict__ ohi, __nv_bfloat16* __restrict__ olo,
                            int R, int C)
{
    __shared__ float tile[32][33];
    const int bx = blockIdx.x * 32, by = blockIdx.y * 32;
    const int tx = threadIdx.x, ty = threadIdx.y;
#pragma unroll
    for (int i = 0; i < 32; i += 8) {
        size_t idx = (size_t)(by + ty + i) * C + bx + tx;
        float v = P0[idx] + P1[idx];
        T[idx] = v;
        tile[ty + i][tx] = v;
    }
    __syncthreads();
#pragma unroll
    for (int i = 0; i < 32; i += 8) {
        float v = tile[tx][ty + i];
        __nv_bfloat16 h = __float2bfloat16(v);
        size_t o = (size_t)(bx + ty + i) * R + by + tx;
        ohi[o] = h;
        olo[o] = __float2bfloat16(v - __bfloat162float(h));
    }
}

// ---------------- combine partials + poly epilogue (+optional row split) -------
// Z = act(h0*Y + h1*T + h2*(P0+P1) + b); if WSPLIT also write bf16 hi/lo of Z.
template <bool RELU, bool WSPLIT>
__global__ void combine_epi_k(const float* __restrict__ P0, const float* __restrict__ P1,
                              const float* __restrict__ Y, const float* __restrict__ T,
                              const float* __restrict__ hv, const float* __restrict__ bias,
                              float* __restrict__ Z,
                              __nv_bfloat16* __restrict__ zhi, __nv_bfloat16* __restrict__ zlo,
                              int nmask)
{
    const size_t i = ((size_t)blockIdx.x * 256 + threadIdx.x) * 4;
    const float c0 = hv[0], c1 = hv[1], c2 = hv[2];
    const float4 p0 = *(const float4*)(P0 + i);
    const float4 p1 = *(const float4*)(P1 + i);
    const float4 y  = *(const float4*)(Y + i);
    const float4 t  = *(const float4*)(T + i);
    const float4 bb = *(const float4*)(bias + (i & nmask));
    float4 v;
    v.x = c0 * y.x + c1 * t.x + c2 * (p0.x + p1.x) + bb.x;
    v.y = c0 * y.y + c1 * t.y + c2 * (p0.y + p1.y) + bb.y;
    v.z = c0 * y.z + c1 * t.z + c2 * (p0.z + p1.z) + bb.z;
    v.w = c0 * y.w + c1 * t.w + c2 * (p0.w + p1.w) + bb.w;
    if (RELU) {
        v.x = fmaxf(v.x, 0.f); v.y = fmaxf(v.y, 0.f);
        v.z = fmaxf(v.z, 0.f); v.w = fmaxf(v.w, 0.f);
    }
    *(float4*)(Z + i) = v;
    if (WSPLIT) {
        uint2 H, L;
        split2(v.x, v.y, H.x, L.x);
        split2(v.z, v.w, H.y, L.y);
        *(uint2*)(zhi + i) = H;
        *(uint2*)(zlo + i) = L;
    }
}

// ---------------- HMMA GEMM, BM=128 (2x64 subtiles), split-K via gridDim.y -----
// C_partial[by][M,BN] = A[M, kslice] x Bt[BN, kslice]
// Partial 'by' is written at C + by * gridDim.x*128*BN  (= by * NROWS*BN here).
template <int BN, int D>
__global__ void __launch_bounds__(256)
tgemm2_k(const __nv_bfloat16* __restrict__ Ahi, const __nv_bfloat16* __restrict__ Alo,
         int lda,
         const __nv_bfloat16* __restrict__ Bhi, const __nv_bfloat16* __restrict__ Blo,
         int ldb, int Ktot, float* __restrict__ C)
{
    extern __shared__ char sm[];
    constexpr int WN = BN / 4;          // warp n extent
    constexpr int NT = WN / 8;          // n8 tiles per warp
    constexpr int ASPL = 128 * 128;     // bytes per A split tile (128 rows x 128 B)
    constexpr int BSPL = BN * 128;
    constexpr int STAGE = 2 * ASPL + 2 * BSPL;

    const int tid = threadIdx.x, wid = tid >> 5, lid = tid & 31;
    const int wm = wid & 1, wn = wid >> 1;
    const int m0 = blockIdx.x * 128;
    const int kslice = Ktot / gridDim.y;
    const int kbase = blockIdx.y * kslice;
    const int nk = kslice / 64;
    float* Cout = C + (size_t)blockIdx.y * (gridDim.x * 128) * BN;
    const uint32_t smb = smem_u32(sm);

    const int ldrow = tid >> 3, ldc = tid & 7;
    const int arl = lid & 15, ahf = lid >> 4;
    const int brl = (lid & 7) + ((lid >> 4) << 3);
    const int bhf = (lid >> 3) & 1;
    const int asw = arl & 7, bsw = lid & 7;

    float acc[2][2][NT][4];
#pragma unroll
    for (int s = 0; s < 2; s++)
#pragma unroll
        for (int mt = 0; mt < 2; mt++)
#pragma unroll
            for (int nt = 0; nt < NT; nt++)
#pragma unroll
                for (int j = 0; j < 4; j++) acc[s][mt][nt][j] = 0.f;

    auto issue = [&](int ch, int buf) {
        const uint32_t sb = smb + buf * STAGE;
        const int kg = kbase + ch * 64;
#pragma unroll
        for (int it = 0; it < 4; it++) {               // A: 128 rows
            const int row = ldrow + 32 * it;
            const size_t go = (size_t)(m0 + row) * lda + kg + ldc * 8;
            const uint32_t so = sb + row * 128 + ((ldc ^ (row & 7)) << 4);
            CP16(so, (const void*)(Ahi + go));
            CP16(so + ASPL, (const void*)(Alo + go));
        }
#pragma unroll
        for (int it = 0; it < BN / 32; it++) {         // B: BN rows
            const int row = ldrow + 32 * it;
            const size_t go = (size_t)row * ldb + kg + ldc * 8;
            const uint32_t so = sb + 2 * ASPL + row * 128 + ((ldc ^ (row & 7)) << 4);
            CP16(so, (const void*)(Bhi + go));
            CP16(so + BSPL, (const void*)(Blo + go));
        }
    };

#pragma unroll
    for (int s = 0; s < D - 1; s++) {
        if (s < nk) issue(s, s);
        CP_COMMIT();
    }

    for (int i = 0; i < nk; i++) {
        CP_WAIT(D - 2);
        __syncthreads();
        if (i + D - 1 < nk) issue(i + D - 1, (i + D - 1) % D);
        CP_COMMIT();

        const uint32_t cab = smb + (i % D) * STAGE;
        const uint32_t cbb = cab + 2 * ASPL;

#pragma unroll
        for (int ks = 0; ks < 4; ks++) {
            uint32_t bH[NT][2], bL[NT][2];
#pragma unroll
            for (int p = 0; p < NT / 2; p++) {
                const uint32_t bo = (uint32_t)((wn * WN + p * 16 + brl) * 128)
                                  + (uint32_t)(((ks * 2 + bhf) ^ bsw) << 4);
                uint32_t t[4];
                LDSM_X4(t, cbb + bo);
                bH[2 * p][0] = t[0]; bH[2 * p][1] = t[1];
                bH[2 * p + 1][0] = t[2]; bH[2 * p + 1][1] = t[3];
                LDSM_X4(t, cbb + BSPL + bo);
                bL[2 * p][0] = t[0]; bL[2 * p][1] = t[1];
                bL[2 * p + 1][0] = t[2]; bL[2 * p + 1][1] = t[3];
            }
#pragma unroll
            for (int sub = 0; sub < 2; sub++) {
                uint32_t aH[2][4], aL[2][4];
#pragma unroll
                for (int mt = 0; mt < 2; mt++) {
                    const uint32_t ao = (uint32_t)((sub * 64 + wm * 32 + mt * 16 + arl) * 128)
                                      + (uint32_t)(((ks * 2 + ahf) ^ asw) << 4);
                    LDSM_X4(aH[mt], cab + ao);
                    LDSM_X4(aL[mt], cab + ASPL + ao);
                }
#pragma unroll
                for (int mt = 0; mt < 2; mt++)
#pragma unroll
                    for (int nt = 0; nt < NT; nt++) {
                        MMA16816(acc[sub][mt][nt], aH[mt], bH[nt]);
                        MMA16816(acc[sub][mt][nt], aH[mt], bL[nt]);
                        MMA16816(acc[sub][mt][nt], aL[mt], bH[nt]);
                    }
            }
        }
    }

    // ---- write partial tile ----
#pragma unroll
    for (int sub = 0; sub < 2; sub++)
#pragma unroll
        for (int mt = 0; mt < 2; mt++)
#pragma unroll
            for (int half = 0; half < 2; half++) {
                const int row = m0 + sub * 64 + wm * 32 + mt * 16 + (lid >> 2) + half * 8;
#pragma unroll
                for (int nt = 0; nt < NT; nt++) {
                    const int col = wn * WN + nt * 8 + (lid & 3) * 2;
                    float2 v = make_float2(acc[sub][mt][nt][half * 2 + 0],
                                           acc[sub][mt][nt][half * 2 + 1]);
                    *(float2*)(Cout + (size_t)row * BN + col) = v;
                }
            }
}

// -------------------------------------------------------------------------------
extern "C" void kernel_launch(void* const* d_in, const int* in_sizes, int n_in,
                              void* d_out, int out_size)
{
    (void)in_sizes; (void)n_in; (void)out_size;
    const float* S  = (const float*)d_in[0];
    const float* X  = (const float*)d_in[1];
    const float* W1 = (const float*)d_in[2];
    const float* h1 = (const float*)d_in[3];
    const float* b1 = (const float*)d_in[4];
    const float* W2 = (const float*)d_in[5];
    const float* h2 = (const float*)d_in[6];
    const float* b2 = (const float*)d_in[7];
    const float* W3 = (const float*)d_in[8];
    const float* h3 = (const float*)d_in[9];
    const float* b3 = (const float*)d_in[10];
    float* out = (float*)d_out;

    float *Y, *T, *Z, *P;
    __nv_bfloat16 *Shi, *Slo, *Ahi, *Alo, *Bhi, *Blo, *Whi, *Wlo;
    cudaGetSymbolAddress((void**)&Y, g_Y);
    cudaGetSymbolAddress((void**)&T, g_T);
    cudaGetSymbolAddress((void**)&Z, g_Z);
    cudaGetSymbolAddress((void**)&P, g_P);
    cudaGetSymbolAddress((void**)&Shi, g_Shi);
    cudaGetSymbolAddress((void**)&Slo, g_Slo);
    cudaGetSymbolAddress((void**)&Ahi, g_Ahi);
    cudaGetSymbolAddress((void**)&Alo, g_Alo);
    cudaGetSymbolAddress((void**)&Bhi, g_Bhi);
    cudaGetSymbolAddress((void**)&Blo, g_Blo);
    cudaGetSymbolAddress((void**)&Whi, g_Whi);
    cudaGetSymbolAddress((void**)&Wlo, g_Wlo);
    float* P0  = P;
    float* P1w = P + (size_t)NROWS * 128;   // partial stride for BN=128 GEMMs
    float* P1n = P + (size_t)NROWS * 64;    // partial stride for BN=64 GEMMs  (R5 bug fix)

    const int SMW = 3 * (2 * 128 * 128 + 2 * 128 * 128);  // 196608 (BN=128, D=3)
    const int SMN = 4 * (2 * 128 * 128 + 2 * 64 * 128);   // 196608 (BN=64,  D=4)
    cudaFuncSetAttribute(tgemm2_k<128, 3>, cudaFuncAttributeMaxDynamicSharedMemorySize, SMW);
    cudaFuncSetAttribute(tgemm2_k<64, 4>,  cudaFuncAttributeMaxDynamicSharedMemorySize, SMN);

    const dim3 blk(256);
    const dim3 tb(32, 8);
    const dim3 gW(NROWS / 128, 1);    // no split-K (narrow X@W)
    const dim3 gS(NROWS / 128, 2);    // split-K2 (S GEMMs)

    // one-time splits
    split_k<<<(size_t)NROWS * NROWS / 2048, 256>>>(S, Shi, Slo);
    split_k<<<NROWS * 512 / 2048, 256>>>(X, Ahi, Alo);

    // ================= Layer 1 =================
    convt_k<<<dim3(4, 16), tb>>>(W1, Whi, Wlo, 512, 128);
    tgemm2_k<128, 3><<<gW, blk, SMW>>>(Ahi, Alo, 512, Whi, Wlo, 512, 512, Y);
    convt_k<<<dim3(4, 256), tb>>>(Y, Bhi, Blo, NROWS, 128);
    tgemm2_k<128, 3><<<gS, blk, SMW>>>(Shi, Slo, NROWS, Bhi, Blo, NROWS, NROWS, P);
    combine_t_k<<<dim3(4, 256), tb>>>(P0, P1w, T, Bhi, Blo, NROWS, 128);
    tgemm2_k<128, 3><<<gS, blk, SMW>>>(Shi, Slo, NROWS, Bhi, Blo, NROWS, NROWS, P);
    combine_epi_k<true, true><<<NROWS * 128 / 1024, 256>>>(P0, P1w, Y, T, h1, b1,
                                                           Z, Ahi, Alo, 127);
    // ================= Layer 2 =================
    convt_k<<<dim3(4, 4), tb>>>(W2, Whi, Wlo, 128, 128);
    tgemm2_k<128, 3><<<gW, blk, SMW>>>(Ahi, Alo, 128, Whi, Wlo, 128, 128, Y);
    convt_k<<<dim3(4, 256), tb>>>(Y, Bhi, Blo, NROWS, 128);
    tgemm2_k<128, 3><<<gS, blk, SMW>>>(Shi, Slo, NROWS, Bhi, Blo, NROWS, NROWS, P);
    combine_t_k<<<dim3(4, 256), tb>>>(P0, P1w, T, Bhi, Blo, NROWS, 128);
    tgemm2_k<128, 3><<<gS, blk, SMW>>>(Shi, Slo, NROWS, Bhi, Blo, NROWS, NROWS, P);
    combine_epi_k<true, true><<<NROWS * 128 / 1024, 256>>>(P0, P1w, Y, T, h2, b2,
                                                           Z, Ahi, Alo, 127);
    // ================= Layer 3 (N=64, no ReLU) =================
    convt_k<<<dim3(2, 4), tb>>>(W3, Whi, Wlo, 128, 64);
    tgemm2_k<64, 4><<<gW, blk, SMN>>>(Ahi, Alo, 128, Whi, Wlo, 128, 128, Y);
    convt_k<<<dim3(2, 256), tb>>>(Y, Bhi, Blo, NROWS, 64);
    tgemm2_k<64, 4><<<gS, blk, SMN>>>(Shi, Slo, NROWS, Bhi, Blo, NROWS, NROWS, P);
    combine_t_k<<<dim3(2, 256), tb>>>(P0, P1n, T, Bhi, Blo, NROWS, 64);
    tgemm2_k<64, 4><<<gS, blk, SMN>>>(Shi, Slo, NROWS, Bhi, Blo, NROWS, NROWS, P);
    combine_epi_k<false, false><<<NROWS * 64 / 1024, 256>>>(P0, P1n, Y, T, h3, b3,
                                                            out, nullptr, nullptr, 63);
}